// round 7
// baseline (speedup 1.0000x reference)
#include <cuda_runtime.h>
#include <cuda_fp16.h>
#include <math.h>
#include <stdint.h>

#define BATCH   16384
#define LATENT  64
#define HID     512
#define OUTD    256
#define KEXP    (HID * 9)    // 4608 = 512 silu + 4096 bases
#define KCH     64           // K-chunk in halves
#define NCH_L   (KEXP / KCH) // 72
#define SILU_CH (HID / KCH)  // 8 chunks of silu region

// ---------------- scratch (device globals; allocation-free rule) ------------
__device__ __half g_xh  [(size_t)BATCH * LATENT];
__device__ __half g_Wdh [(size_t)HID * LATENT];
__device__ __half g_W1  [(size_t)HID  * KEXP];
__device__ __half g_W2  [(size_t)OUTD * KEXP];
__device__ float  g_hT_a[(size_t)HID * BATCH];   // h transposed (layer input), set A
__device__ float  g_hT_b[(size_t)HID * BATCH];   // set B
__device__ __half g_ps_a[(size_t)BATCH * HID];   // silu(h) fp16, set A
__device__ __half g_ps_b[(size_t)BATCH * HID];   // set B

// ---------------- helpers -----------------------------------------------------
__device__ __forceinline__ uint32_t smem_u32(const void* p) {
    uint32_t a;
    asm("{ .reg .u64 t; cvta.to.shared.u64 t, %1; cvt.u32.u64 %0, t; }" : "=r"(a) : "l"(p));
    return a;
}
__device__ __forceinline__ void cp16(uint32_t dst, const void* src) {
    asm volatile("cp.async.cg.shared.global [%0], [%1], 16;" :: "r"(dst), "l"(src));
}
__device__ __forceinline__ void ldm_x4(uint32_t* r, uint32_t addr) {
    asm volatile("ldmatrix.sync.aligned.m8n8.x4.shared.b16 {%0,%1,%2,%3}, [%4];"
        : "=r"(r[0]), "=r"(r[1]), "=r"(r[2]), "=r"(r[3]) : "r"(addr));
}
__device__ __forceinline__ void mma_f16(float* d, const uint32_t* a, uint32_t b0, uint32_t b1) {
    asm volatile(
        "mma.sync.aligned.m16n8k16.row.col.f32.f16.f16.f32 "
        "{%0,%1,%2,%3}, {%4,%5,%6,%7}, {%8,%9}, {%0,%1,%2,%3};"
        : "+f"(d[0]), "+f"(d[1]), "+f"(d[2]), "+f"(d[3])
        : "r"(a[0]), "r"(a[1]), "r"(a[2]), "r"(a[3]), "r"(b0), "r"(b1));
}
__device__ __forceinline__ void sts8(uint32_t addr, uint32_t v0, uint32_t v1) {
    asm volatile("st.shared.v2.b32 [%0], {%1,%2};" :: "r"(addr), "r"(v0), "r"(v1));
}
__device__ __forceinline__ uint32_t h2_bits(float a, float b) {
    __half2 h = __floats2half2_rn(a, b);
    uint32_t u;
    memcpy(&u, &h, 4);
    return u;
}

// Cox-de Boor cubic bases (matches reference exactly), packed to 4x half2
__device__ __forceinline__ void bases8(float xv, uint32_t out[4]) {
    float g[12];
#pragma unroll
    for (int j = 0; j < 12; j++)
        g[j] = __fadd_rn(__fmul_rn((float)(j - 3), 0.4f), -1.0f);
    float bas[11];
#pragma unroll
    for (int j = 0; j < 11; j++)
        bas[j] = (xv >= g[j] && xv < g[j + 1]) ? 1.0f : 0.0f;
#pragma unroll
    for (int k = 1; k <= 3; k++) {
#pragma unroll
        for (int j = 0; j < 11 - k; j++) {
            float left  = (xv - g[j])         / (g[j + k]     - g[j])     * bas[j];
            float right = (g[j + k + 1] - xv) / (g[j + k + 1] - g[j + 1]) * bas[j + 1];
            bas[j] = left + right;
        }
    }
#pragma unroll
    for (int p = 0; p < 4; p++)
        out[p] = h2_bits(bas[2 * p], bas[2 * p + 1]);
}

// ---------------- prep kernels ------------------------------------------------
__global__ void prep_xh(const float* __restrict__ x, __half* __restrict__ xh, int n) {
    int i = blockIdx.x * blockDim.x + threadIdx.x;
    if (i < n) xh[i] = __float2half_rn(x[i]);
}
// K order: [ silu: k=i (512) | bases: k=512+i*8+g (4096) ]
__global__ void prep_kan(const float* __restrict__ bw, const float* __restrict__ sw,
                         const float* __restrict__ sc, __half* __restrict__ Wt, int N) {
    int idx = blockIdx.x * blockDim.x + threadIdx.x;
    if (idx >= N * HID) return;
    int o = idx / HID, i = idx % HID;
    float s = sc[(size_t)o * HID + i];
    Wt[(size_t)o * KEXP + i] = __float2half_rn(bw[(size_t)o * HID + i]);
    size_t base = (size_t)o * KEXP + HID + (size_t)i * 8;
#pragma unroll
    for (int g = 0; g < 8; g++)
        Wt[base + g] = __float2half_rn(sw[((size_t)o * HID + i) * 8 + g] * s);
}

// ---------------- fused fp16 mma GEMM -----------------------------------------
// C[M,N] = A[M,K] * W[N,K]^T.  Block 128x256, 512 thr, warp tile 32x64.
// A-chunks < SILU_E come via cp.async from Aplain (stride SA); chunks >= SILU_E
// are spline bases computed in-kernel from hT_src (fp32, transposed).
// EPI: 0 = plain store to C; 1 = v=silu(acc+bias), emit hT+phis; 2 = v=acc, emit hT+phis.
#define PITCHW  36
#define A_W     (128 * PITCHW)
#define B_W     (256 * PITCHW)
#define BUF_W   (A_W + B_W)
#define SMEM_BYTES (3 * BUF_W * 4)        // 165888

template <int NCHUNK_T, int SILU_E, int EPI>
__global__ __launch_bounds__(512, 1) void gemm_mma(
    const __half* __restrict__ Aplain, int SA,
    const float* __restrict__ hT_src,
    const __half* __restrict__ W,
    const float* __restrict__ bias,
    float* __restrict__ C, float* __restrict__ hT_dst, __half* __restrict__ phis_dst,
    int N)
{
    constexpr int K = NCHUNK_T * KCH;
    extern __shared__ __align__(16) uint32_t smu[];
    const uint32_t sbase = smem_u32(smu);

    const int tid  = threadIdx.x;
    const int wid  = tid >> 5, lane = tid & 31;
    const int wm   = wid & 3;
    const int wn   = wid >> 2;
    const int bm   = blockIdx.y * 128;
    const int bn   = blockIdx.x * 256;

    const uint32_t laneRow = lane & 15;
    const uint32_t laneKB  = (lane >> 4) * 16;
    const uint32_t aLaneOff = (wm * 32 + laneRow) * (PITCHW * 4) + laneKB;
    const uint32_t bLaneOff = A_W * 4 + (wn * 64 + laneRow) * (PITCHW * 4) + laneKB;

    // cp.async geometry for A (silu region) and B
    const int ar0 = tid >> 3,         ac0 = (tid & 7) << 3;
    const int ar1 = (tid + 512) >> 3, ac1 = ((tid + 512) & 7) << 3;
    const __half* aSrc0 = Aplain + (size_t)(bm + ar0) * SA + ac0;
    const __half* aSrc1 = Aplain + (size_t)(bm + ar1) * SA + ac1;
    const __half* bSrc[4];
    int bn_[4], bc_[4];
#pragma unroll
    for (int i = 0; i < 4; i++) {
        int v = tid + i * 512;
        bn_[i] = v >> 3; bc_[i] = (v & 7) << 3;
        bSrc[i] = W + (size_t)(bn + bn_[i]) * K + bc_[i];
    }
    const uint32_t aDst0 = (ar0 * PITCHW + (ac0 >> 1)) * 4;
    const uint32_t aDst1 = (ar1 * PITCHW + (ac1 >> 1)) * 4;
    uint32_t bDst[4];
#pragma unroll
    for (int i = 0; i < 4; i++) bDst[i] = (A_W + bn_[i] * PITCHW + (bc_[i] >> 1)) * 4;

    // bases-fill geometry: thread owns row pr, input slots pi and pi+4
    const int pr = tid & 127;
    const int pi = tid >> 7;        // 0..3
    float xreg[2][2];               // [chunk parity][slot]

    float acc[2][8][4];
#pragma unroll
    for (int mt = 0; mt < 2; mt++)
#pragma unroll
        for (int nt = 0; nt < 8; nt++)
#pragma unroll
            for (int i = 0; i < 4; i++) acc[mt][nt][i] = 0.0f;

    // prologue: chunks 0,1 (always plain region for our launches)
#pragma unroll
    for (int c = 0; c < 2; c++) {
        if (c < NCHUNK_T) {
            uint32_t bb = sbase + c * BUF_W * 4;
            cp16(bb + aDst0, aSrc0 + c * KCH);
            cp16(bb + aDst1, aSrc1 + c * KCH);
#pragma unroll
            for (int i = 0; i < 4; i++) cp16(bb + bDst[i], bSrc[i] + c * KCH);
        }
        asm volatile("cp.async.commit_group;");
    }

    int buf = 0;
    for (int c = 0; c < NCHUNK_T; c++) {
        asm volatile("cp.async.wait_group 1;");

        // STS-fill bases for this chunk (regs prefetched 2 iters ago)
        if (c >= SILU_E) {
            uint32_t bb = sbase + buf * BUF_W * 4;
            uint32_t pk[4];
            bases8(xreg[c & 1][0], pk);
            uint32_t off = bb + pr * (PITCHW * 4) + pi * 16;
            sts8(off,     pk[0], pk[1]);
            sts8(off + 8, pk[2], pk[3]);
            bases8(xreg[c & 1][1], pk);
            off += 64;   // (pi+4)*16
            sts8(off,     pk[0], pk[1]);
            sts8(off + 8, pk[2], pk[3]);
        }
        __syncthreads();

        // stage chunk c+2
        {
            int cc = c + 2;
            if (cc < NCHUNK_T) {
                int nb = buf + 2; if (nb >= 3) nb -= 3;
                uint32_t bb = sbase + nb * BUF_W * 4;
                if (cc < SILU_E) {
                    cp16(bb + aDst0, aSrc0 + cc * KCH);
                    cp16(bb + aDst1, aSrc1 + cc * KCH);
                } else {
                    int i0 = (cc - SILU_E) * 8;
                    xreg[cc & 1][0] = hT_src[(size_t)(i0 + pi)     * BATCH + bm + pr];
                    xreg[cc & 1][1] = hT_src[(size_t)(i0 + pi + 4) * BATCH + bm + pr];
                }
#pragma unroll
                for (int i = 0; i < 4; i++) cp16(bb + bDst[i], bSrc[i] + cc * KCH);
            }
            asm volatile("cp.async.commit_group;");
        }

        const uint32_t base = sbase + buf * BUF_W * 4;
#pragma unroll
        for (int kt = 0; kt < 4; kt++) {
            uint32_t a[2][4], b[4][4];
            ldm_x4(a[0], base + aLaneOff + kt * 32);
            ldm_x4(a[1], base + aLaneOff + 16 * PITCHW * 4 + kt * 32);
#pragma unroll
            for (int p = 0; p < 4; p++)
                ldm_x4(b[p], base + bLaneOff + p * 16 * PITCHW * 4 + kt * 32);
#pragma unroll
            for (int p = 0; p < 4; p++) {
                mma_f16(acc[0][2 * p],     a[0], b[p][0], b[p][2]);
                mma_f16(acc[1][2 * p],     a[1], b[p][0], b[p][2]);
                mma_f16(acc[0][2 * p + 1], a[0], b[p][1], b[p][3]);
                mma_f16(acc[1][2 * p + 1], a[1], b[p][1], b[p][3]);
            }
        }
        buf++; if (buf == 3) buf = 0;
    }

    // epilogue
    const int g = lane >> 2, t = lane & 3;
#pragma unroll
    for (int mt = 0; mt < 2; mt++) {
        int row0 = bm + wm * 32 + mt * 16 + g;
#pragma unroll
        for (int nt = 0; nt < 8; nt++) {
            int col = bn + wn * 64 + nt * 8 + 2 * t;
#pragma unroll
            for (int hrow = 0; hrow < 2; hrow++) {
                int row = row0 + 8 * hrow;
                float v0 = acc[mt][nt][2 * hrow + 0];
                float v1 = acc[mt][nt][2 * hrow + 1];
                if (EPI == 0) {
                    *(float2*)(C + (size_t)row * N + col) = make_float2(v0, v1);
                } else {
                    if (EPI == 1) {
                        v0 += bias[col];     v1 += bias[col + 1];
                        v0 = v0 / (1.0f + expf(-v0));
                        v1 = v1 / (1.0f + expf(-v1));
                    }
                    hT_dst[(size_t)col       * BATCH + row] = v0;
                    hT_dst[(size_t)(col + 1) * BATCH + row] = v1;
                    float s0 = v0 / (1.0f + expf(-v0));
                    float s1 = v1 / (1.0f + expf(-v1));
                    __half2 sh = __floats2half2_rn(s0, s1);
                    *(__half2*)(phis_dst + (size_t)row * HID + col) = sh;
                }
            }
        }
    }
}

// ---------------- launch ------------------------------------------------------
extern "C" void kernel_launch(void* const* d_in, const int* in_sizes, int n_in,
                              void* d_out, int out_size) {
    const float* x   = (const float*)d_in[0];
    const float* dw  = (const float*)d_in[1];
    const float* db  = (const float*)d_in[2];
    const float* bw1 = (const float*)d_in[3];
    const float* sw1 = (const float*)d_in[4];
    const float* sc1 = (const float*)d_in[5];
    const float* bw2 = (const float*)d_in[6];
    const float* sw2 = (const float*)d_in[7];
    const float* sc2 = (const float*)d_in[8];
    float* out = (float*)d_out;

    __half *p_xh, *p_Wdh, *p_W1, *p_W2, *p_psa, *p_psb;
    float  *p_hTa, *p_hTb;
    cudaGetSymbolAddress((void**)&p_xh,  g_xh);
    cudaGetSymbolAddress((void**)&p_Wdh, g_Wdh);
    cudaGetSymbolAddress((void**)&p_W1,  g_W1);
    cudaGetSymbolAddress((void**)&p_W2,  g_W2);
    cudaGetSymbolAddress((void**)&p_hTa, g_hT_a);
    cudaGetSymbolAddress((void**)&p_hTb, g_hT_b);
    cudaGetSymbolAddress((void**)&p_psa, g_ps_a);
    cudaGetSymbolAddress((void**)&p_psb, g_ps_b);

    cudaFuncSetAttribute(gemm_mma<1, 9999, 1>,        cudaFuncAttributeMaxDynamicSharedMemorySize, SMEM_BYTES);
    cudaFuncSetAttribute(gemm_mma<NCH_L, SILU_CH, 2>, cudaFuncAttributeMaxDynamicSharedMemorySize, SMEM_BYTES);
    cudaFuncSetAttribute(gemm_mma<NCH_L, SILU_CH, 0>, cudaFuncAttributeMaxDynamicSharedMemorySize, SMEM_BYTES);

    prep_xh<<<(BATCH * LATENT + 255) / 256, 256>>>(x, p_xh, BATCH * LATENT);
    prep_xh<<<(HID * LATENT + 255) / 256, 256>>>(dw, p_Wdh, HID * LATENT);
    prep_kan<<<(HID * HID + 255) / 256, 256>>>(bw1, sw1, sc1, p_W1, HID);
    prep_kan<<<(OUTD * HID + 255) / 256, 256>>>(bw2, sw2, sc2, p_W2, OUTD);

    // prelude: h0 = silu(x @ dense_w^T + b) -> hT_a + phis_a
    gemm_mma<1, 9999, 1><<<dim3(HID / 256, BATCH / 128), 512, SMEM_BYTES>>>(
        p_xh, LATENT, nullptr, p_Wdh, db, nullptr, p_hTa, p_psa, HID);

    // layer 1 (fused expansion): reads phis_a + hT_a -> hT_b + phis_b
    gemm_mma<NCH_L, SILU_CH, 2><<<dim3(HID / 256, BATCH / 128), 512, SMEM_BYTES>>>(
        p_psa, HID, p_hTa, p_W1, nullptr, nullptr, p_hTb, p_psb, HID);

    // layer 2 (fused expansion): reads phis_b + hT_b -> out
    gemm_mma<NCH_L, SILU_CH, 0><<<dim3(OUTD / 256, BATCH / 128), 512, SMEM_BYTES>>>(
        p_psb, HID, p_hTb, p_W2, nullptr, out, nullptr, nullptr, OUTD);
}

// round 8
// speedup vs baseline: 1.5063x; 1.5063x over previous
#include <cuda_runtime.h>
#include <cuda_fp16.h>
#include <math.h>
#include <stdint.h>

#define BATCH   16384
#define LATENT  64
#define HID     512
#define OUTD    256
#define KEXP    (HID * 9)    // 4608
#define KCH     64           // K-chunk in halves
#define NCH_L   (KEXP / KCH) // 72

// ---------------- scratch (device globals; allocation-free rule) ------------
__device__ float  g_h  [(size_t)BATCH * HID];
__device__ __half g_phi[(size_t)BATCH * KEXP];
__device__ __half g_xh [(size_t)BATCH * LATENT];
__device__ __half g_Wdh[(size_t)HID * LATENT];
__device__ __half g_W1 [(size_t)HID  * KEXP];
__device__ __half g_W2 [(size_t)OUTD * KEXP];

// ---------------- helpers -----------------------------------------------------
__device__ __forceinline__ uint32_t smem_u32(const void* p) {
    uint32_t a;
    asm("{ .reg .u64 t; cvta.to.shared.u64 t, %1; cvt.u32.u64 %0, t; }" : "=r"(a) : "l"(p));
    return a;
}
__device__ __forceinline__ void cp16(uint32_t dst, const void* src) {
    asm volatile("cp.async.cg.shared.global [%0], [%1], 16;" :: "r"(dst), "l"(src));
}
__device__ __forceinline__ void ldm_x4(uint32_t* r, uint32_t addr) {
    asm volatile("ldmatrix.sync.aligned.m8n8.x4.shared.b16 {%0,%1,%2,%3}, [%4];"
        : "=r"(r[0]), "=r"(r[1]), "=r"(r[2]), "=r"(r[3]) : "r"(addr));
}
__device__ __forceinline__ void mma_f16(float* d, const uint32_t* a, uint32_t b0, uint32_t b1) {
    asm volatile(
        "mma.sync.aligned.m16n8k16.row.col.f32.f16.f16.f32 "
        "{%0,%1,%2,%3}, {%4,%5,%6,%7}, {%8,%9}, {%0,%1,%2,%3};"
        : "+f"(d[0]), "+f"(d[1]), "+f"(d[2]), "+f"(d[3])
        : "r"(a[0]), "r"(a[1]), "r"(a[2]), "r"(a[3]), "r"(b0), "r"(b1));
}

// ---------------- prep kernels ------------------------------------------------
__global__ void prep_xh(const float* __restrict__ x, __half* __restrict__ xh, int n) {
    int i = blockIdx.x * blockDim.x + threadIdx.x;
    if (i < n) xh[i] = __float2half_rn(x[i]);
}
// N x K, K order: i*9 + {silu, bases0..7}
__global__ void prep_kan(const float* __restrict__ bw, const float* __restrict__ sw,
                         const float* __restrict__ sc, __half* __restrict__ Wt, int N) {
    int idx = blockIdx.x * blockDim.x + threadIdx.x;
    if (idx >= N * HID) return;
    int o = idx / HID, i = idx % HID;
    float s = sc[(size_t)o * HID + i];
    size_t base = (size_t)o * KEXP + (size_t)i * 9;
    Wt[base] = __float2half_rn(bw[(size_t)o * HID + i]);
#pragma unroll
    for (int g = 0; g < 8; g++)
        Wt[base + 1 + g] = __float2half_rn(sw[((size_t)o * HID + i) * 8 + g] * s);
}

// ---------------- expand: h -> [silu(h), B-splines(h)] fp16 -------------------
__global__ void expand_kernel(const float* __restrict__ h, __half* __restrict__ phi) {
    int idx = blockIdx.x * blockDim.x + threadIdx.x;
    if (idx >= BATCH * HID) return;
    float xv = h[idx];

    float g[12];
#pragma unroll
    for (int j = 0; j < 12; j++)
        g[j] = __fadd_rn(__fmul_rn((float)(j - 3), 0.4f), -1.0f);

    float bas[11];
#pragma unroll
    for (int j = 0; j < 11; j++)
        bas[j] = (xv >= g[j] && xv < g[j + 1]) ? 1.0f : 0.0f;
#pragma unroll
    for (int k = 1; k <= 3; k++) {
#pragma unroll
        for (int j = 0; j < 11 - k; j++) {
            float left  = (xv - g[j])         / (g[j + k]     - g[j])     * bas[j];
            float right = (g[j + k + 1] - xv) / (g[j + k + 1] - g[j + 1]) * bas[j + 1];
            bas[j] = left + right;
        }
    }
    float si = xv / (1.0f + expf(-xv));
    size_t base = (size_t)idx * 9;
    phi[base] = __float2half_rn(si);
#pragma unroll
    for (int gg = 0; gg < 8; gg++) phi[base + 1 + gg] = __float2half_rn(bas[gg]);
}

// ---------------- fp16 mma GEMM: C[M,N] = A[M,K] * W[N,K]^T -------------------
// Block 128x128, BK=64 halves, 256 threads (8 warps: 4 wm x 2 wn),
// warp tile 32x64. 3-stage cp.async, 1 sync/chunk, 2 CTAs/SM.
// EPI==1: C = silu(acc + bias[col]).
#define PITCHW  36
#define A_W     (128 * PITCHW)
#define B_W     (128 * PITCHW)
#define BUF_W   (A_W + B_W)               // 9216 words = 36864 B
#define SMEM_BYTES (3 * BUF_W * 4)        // 110592

template <int NCHUNK_T, int EPI>
__global__ __launch_bounds__(256, 2) void gemm_mma(
    const __half* __restrict__ A, const __half* __restrict__ W,
    const float* __restrict__ bias, float* __restrict__ C, int N)
{
    constexpr int K = NCHUNK_T * KCH;
    extern __shared__ __align__(16) uint32_t smu[];
    const uint32_t sbase = smem_u32(smu);

    const int tid  = threadIdx.x;
    const int wid  = tid >> 5, lane = tid & 31;
    const int wm   = wid & 3;          // warp row (x32)
    const int wn   = wid >> 2;         // warp col (x64), 0..1
    const int bm   = blockIdx.y * 128;
    const int bn   = blockIdx.x * 128;

    const uint32_t laneRow = lane & 15;
    const uint32_t laneKB  = (lane >> 4) * 16;
    const uint32_t aLaneOff = (wm * 32 + laneRow) * (PITCHW * 4) + laneKB;
    const uint32_t bLaneOff = A_W * 4 + (wn * 64 + laneRow) * (PITCHW * 4) + laneKB;

    // cp.async: A tile 128x64h = 1024 vec16, B same. 4 each per thread.
    const __half* aSrc[4];
    const __half* bSrc[4];
    uint32_t aDst[4], bDst[4];
#pragma unroll
    for (int i = 0; i < 4; i++) {
        int v = tid + i * 256;
        int r = v >> 3, cHalf = (v & 7) << 3;
        aSrc[i] = A + (size_t)(bm + r) * K + cHalf;
        bSrc[i] = W + (size_t)(bn + r) * K + cHalf;
        aDst[i] = (r * PITCHW + (cHalf >> 1)) * 4;
        bDst[i] = (A_W + r * PITCHW + (cHalf >> 1)) * 4;
    }

    float acc[2][8][4];
#pragma unroll
    for (int mt = 0; mt < 2; mt++)
#pragma unroll
        for (int nt = 0; nt < 8; nt++)
#pragma unroll
            for (int i = 0; i < 4; i++) acc[mt][nt][i] = 0.0f;

    // prologue: stage chunks 0,1
#pragma unroll
    for (int c = 0; c < 2; c++) {
        if (c < NCHUNK_T) {
            uint32_t bb = sbase + c * BUF_W * 4;
#pragma unroll
            for (int i = 0; i < 4; i++) {
                cp16(bb + aDst[i], aSrc[i] + c * KCH);
                cp16(bb + bDst[i], bSrc[i] + c * KCH);
            }
        }
        asm volatile("cp.async.commit_group;");
    }

    int buf = 0;
    for (int c = 0; c < NCHUNK_T; c++) {
        asm volatile("cp.async.wait_group 1;");
        __syncthreads();

        // stage chunk c+2 into buffer (c+2)%3
        {
            int cc = c + 2;
            if (cc < NCHUNK_T) {
                int nb = buf + 2; if (nb >= 3) nb -= 3;
                uint32_t bb = sbase + nb * BUF_W * 4;
                int off = cc * KCH;
#pragma unroll
                for (int i = 0; i < 4; i++) {
                    cp16(bb + aDst[i], aSrc[i] + off);
                    cp16(bb + bDst[i], bSrc[i] + off);
                }
            }
            asm volatile("cp.async.commit_group;");
        }

        const uint32_t base = sbase + buf * BUF_W * 4;
#pragma unroll
        for (int kt = 0; kt < 4; kt++) {
            uint32_t a[2][4], b[4][4];
            ldm_x4(a[0], base + aLaneOff + kt * 32);
            ldm_x4(a[1], base + aLaneOff + 16 * PITCHW * 4 + kt * 32);
#pragma unroll
            for (int p = 0; p < 4; p++)
                ldm_x4(b[p], base + bLaneOff + p * 16 * PITCHW * 4 + kt * 32);
#pragma unroll
            for (int p = 0; p < 4; p++) {
                mma_f16(acc[0][2 * p],     a[0], b[p][0], b[p][2]);
                mma_f16(acc[1][2 * p],     a[1], b[p][0], b[p][2]);
                mma_f16(acc[0][2 * p + 1], a[0], b[p][1], b[p][3]);
                mma_f16(acc[1][2 * p + 1], a[1], b[p][1], b[p][3]);
            }
        }
        buf++; if (buf == 3) buf = 0;
    }

    // epilogue
    const int g = lane >> 2, t = lane & 3;
#pragma unroll
    for (int mt = 0; mt < 2; mt++) {
        int row0 = bm + wm * 32 + mt * 16 + g;
#pragma unroll
        for (int nt = 0; nt < 8; nt++) {
            int col = bn + wn * 64 + nt * 8 + 2 * t;
#pragma unroll
            for (int hrow = 0; hrow < 2; hrow++) {
                int row = row0 + 8 * hrow;
                float v0 = acc[mt][nt][2 * hrow + 0];
                float v1 = acc[mt][nt][2 * hrow + 1];
                if (EPI == 1) {
                    v0 += bias[col];     v1 += bias[col + 1];
                    v0 = v0 / (1.0f + expf(-v0));
                    v1 = v1 / (1.0f + expf(-v1));
                }
                *(float2*)(C + (size_t)row * N + col) = make_float2(v0, v1);
            }
        }
    }
}

// ---------------- launch ------------------------------------------------------
extern "C" void kernel_launch(void* const* d_in, const int* in_sizes, int n_in,
                              void* d_out, int out_size) {
    const float* x   = (const float*)d_in[0];
    const float* dw  = (const float*)d_in[1];
    const float* db  = (const float*)d_in[2];
    const float* bw1 = (const float*)d_in[3];
    const float* sw1 = (const float*)d_in[4];
    const float* sc1 = (const float*)d_in[5];
    const float* bw2 = (const float*)d_in[6];
    const float* sw2 = (const float*)d_in[7];
    const float* sc2 = (const float*)d_in[8];
    float* out = (float*)d_out;

    float  *p_h;
    __half *p_phi, *p_xh, *p_Wdh, *p_W1, *p_W2;
    cudaGetSymbolAddress((void**)&p_h,   g_h);
    cudaGetSymbolAddress((void**)&p_phi, g_phi);
    cudaGetSymbolAddress((void**)&p_xh,  g_xh);
    cudaGetSymbolAddress((void**)&p_Wdh, g_Wdh);
    cudaGetSymbolAddress((void**)&p_W1,  g_W1);
    cudaGetSymbolAddress((void**)&p_W2,  g_W2);

    cudaFuncSetAttribute(gemm_mma<NCH_L, 0>, cudaFuncAttributeMaxDynamicSharedMemorySize, SMEM_BYTES);
    cudaFuncSetAttribute(gemm_mma<1, 1>,     cudaFuncAttributeMaxDynamicSharedMemorySize, SMEM_BYTES);

    prep_xh<<<(BATCH * LATENT + 255) / 256, 256>>>(x, p_xh, BATCH * LATENT);
    prep_xh<<<(HID * LATENT + 255) / 256, 256>>>(dw, p_Wdh, HID * LATENT);
    prep_kan<<<(HID * HID + 255) / 256, 256>>>(bw1, sw1, sc1, p_W1, HID);
    prep_kan<<<(OUTD * HID + 255) / 256, 256>>>(bw2, sw2, sc2, p_W2, OUTD);

    // prelude: h0 = silu(x @ dense_w^T + b)
    gemm_mma<1, 1><<<dim3(HID / 128, BATCH / 128), 256, SMEM_BYTES>>>(
        p_xh, p_Wdh, db, p_h, HID);

    int expBlocks = (BATCH * HID + 255) / 256;

    // layer 1
    expand_kernel<<<expBlocks, 256>>>(p_h, p_phi);
    gemm_mma<NCH_L, 0><<<dim3(HID / 128, BATCH / 128), 256, SMEM_BYTES>>>(
        p_phi, p_W1, nullptr, p_h, HID);
    // layer 2
    expand_kernel<<<expBlocks, 256>>>(p_h, p_phi);
    gemm_mma<NCH_L, 0><<<dim3(OUTD / 128, BATCH / 128), 256, SMEM_BYTES>>>(
        p_phi, p_W2, nullptr, out, OUTD);
}